// round 2
// baseline (speedup 1.0000x reference)
#include <cuda_runtime.h>
#include <cstdint>

// ---------------------------------------------------------------------------
// BiARMA (2-layer ARMA GCN), N=100000, E=1e6, 128 -> 64 -> 40.
//
// dinv = rsqrt(deg(col)), 0 where deg==0
// g1   = dinv * (x @ W1i)            S1[c] += g1[r]  over edges
// out1 = relu(dinv*S1 + x @ W1r + b1)
// g2   = dinv * (out1 @ W2i)         S2[c] += g2[r]
// out  = relu(dinv*S2 + out1 @ W2r + b2)
//
// Scratch kept minimal (58 MB) to survive tight container VRAM headroom:
//   g_dinv [N]      deg then dinv (in place)
//   g_bufA [64N]    g1, later out1
//   g_bufB [80N]    S1 in [0,64N); then g2 in [0,40N) + S2 in [40N,80N)
// ---------------------------------------------------------------------------

static constexpr int MAXN = 100000;

__device__ float g_dinv[MAXN];
__device__ float g_bufA[MAXN * 64];
__device__ float g_bufB[MAXN * 80];

// ---------------------------------------------------------------------------
__global__ void deg_kernel(const int* __restrict__ col, float* __restrict__ deg, int E) {
    int i = blockIdx.x * blockDim.x + threadIdx.x;
    if (i < E) atomicAdd(&deg[col[i]], 1.0f);
}

__global__ void dinv_kernel(float* __restrict__ d, int N) {
    int i = blockIdx.x * blockDim.x + threadIdx.x;
    if (i < N) {
        float v = d[i];
        d[i] = (v > 0.0f) ? rsqrtf(v) : 0.0f;
    }
}

// ---------------------------------------------------------------------------
// GEMM with epilogue.  X:[N,K] row-major, W:[K,NC] row-major.
// POST=false: O[n] = dinv[n] * (X@W)[n]
// POST=true : O[n] = relu(dinv[n]*S[n] + (X@W)[n] + b)
// 64 nodes/block; thread computes 4 nodes x 4 cols.  Threads = 16*(NC/4).
// ---------------------------------------------------------------------------
template <int K, int NC, bool POST>
__global__ void __launch_bounds__(16 * (NC / 4))
gemm_epi(const float* __restrict__ X, const float* __restrict__ W,
         const float* __restrict__ B, const float* __restrict__ dinv,
         const float* __restrict__ S, float* __restrict__ O, int N)
{
    constexpr int NCG  = NC / 4;
    constexpr int NTHR = 16 * NCG;
    constexpr int XP   = 68;                 // padded node stride (bank-conflict free)

    extern __shared__ float sm[];
    float* xT = sm;                          // [K][XP]
    float* ws = sm + K * XP;                 // [K][NC]

    const int tid  = threadIdx.x;
    const int base = blockIdx.x * 64;

    for (int i = tid; i < K * NC; i += NTHR) ws[i] = W[i];

    for (int i = tid; i < 64 * K; i += NTHR) {
        int nl = i / K, k = i - nl * K;      // consecutive tid -> consecutive k (coalesced)
        int node = base + nl;
        xT[k * XP + nl] = (node < N) ? X[node * K + k] : 0.0f;
    }
    __syncthreads();

    const int ng = tid / NCG;                // 0..15 node group
    const int cg = tid - ng * NCG;           // 0..NCG-1 col group

    float acc[4][4];
#pragma unroll
    for (int i = 0; i < 4; i++)
#pragma unroll
        for (int j = 0; j < 4; j++) acc[i][j] = 0.0f;

    const float* xp = xT + ng * 4;
    const float* wp = ws + cg * 4;

#pragma unroll 8
    for (int k = 0; k < K; ++k) {
        float4 a = *reinterpret_cast<const float4*>(xp + k * XP);
        float4 b = *reinterpret_cast<const float4*>(wp + k * NC);
        float av[4] = {a.x, a.y, a.z, a.w};
#pragma unroll
        for (int i = 0; i < 4; i++) {
            acc[i][0] += av[i] * b.x; acc[i][1] += av[i] * b.y;
            acc[i][2] += av[i] * b.z; acc[i][3] += av[i] * b.w;
        }
    }

    float4 bb = make_float4(0.f, 0.f, 0.f, 0.f);
    if (POST) bb = *reinterpret_cast<const float4*>(B + cg * 4);

#pragma unroll
    for (int i = 0; i < 4; i++) {
        int node = base + ng * 4 + i;
        if (node < N) {
            float dv = dinv[node];
            float4 o;
            if (POST) {
                float4 s = *reinterpret_cast<const float4*>(S + node * NC + cg * 4);
                o.x = fmaxf(fmaf(dv, s.x, acc[i][0] + bb.x), 0.0f);
                o.y = fmaxf(fmaf(dv, s.y, acc[i][1] + bb.y), 0.0f);
                o.z = fmaxf(fmaf(dv, s.z, acc[i][2] + bb.z), 0.0f);
                o.w = fmaxf(fmaf(dv, s.w, acc[i][3] + bb.w), 0.0f);
            } else {
                o = make_float4(acc[i][0] * dv, acc[i][1] * dv,
                                acc[i][2] * dv, acc[i][3] * dv);
            }
            *reinterpret_cast<float4*>(O + node * NC + cg * 4) = o;
        }
    }
}

// ---------------------------------------------------------------------------
// Edge scatter: S[col] += G[row]   (F = 4*FQ floats/node)
// One thread per (edge, float4 chunk); fire-and-forget vector reduction.
// ---------------------------------------------------------------------------
template <int FQ>
__global__ void scatter_add(const int* __restrict__ rowi, const int* __restrict__ coli,
                            const float* __restrict__ G, float* __restrict__ S, int total)
{
    int idx = blockIdx.x * blockDim.x + threadIdx.x;
    if (idx >= total) return;
    int e = idx / FQ;
    int c = idx - e * FQ;
    int r  = __ldg(rowi + e);
    int cl = __ldg(coli + e);
    float4 v = __ldg(reinterpret_cast<const float4*>(G + (r * FQ + c) * 4));
    float* p = S + (cl * FQ + c) * 4;
    asm volatile("red.global.add.v4.f32 [%0], {%1,%2,%3,%4};"
                 :: "l"(p), "f"(v.x), "f"(v.y), "f"(v.z), "f"(v.w) : "memory");
}

// ---------------------------------------------------------------------------
extern "C" void kernel_launch(void* const* d_in, const int* in_sizes, int n_in,
                              void* d_out, int out_size)
{
    const float* x   = (const float*)d_in[0];
    const int*   ei  = (const int*)  d_in[1];
    const float* w1i = (const float*)d_in[2];
    const float* w1r = (const float*)d_in[3];
    const float* b1  = (const float*)d_in[4];
    const float* w2i = (const float*)d_in[5];
    const float* w2r = (const float*)d_in[6];
    const float* b2  = (const float*)d_in[7];
    float* out = (float*)d_out;

    const int E = in_sizes[1] / 2;
    const int N = out_size / 40;
    const int* row = ei;
    const int* col = ei + E;

    float *pdinv, *pA, *pB;
    cudaGetSymbolAddress((void**)&pdinv, g_dinv);
    cudaGetSymbolAddress((void**)&pA,    g_bufA);
    cudaGetSymbolAddress((void**)&pB,    g_bufB);

    // deg -> dinv (in place)
    cudaMemsetAsync(pdinv, 0, (size_t)N * sizeof(float));
    deg_kernel <<<(E + 255) / 256, 256>>>(col, pdinv, E);
    dinv_kernel<<<(N + 255) / 256, 256>>>(pdinv, N);

    // ---- Layer 1 ----
    const int smem1 = (128 * 68 + 128 * 64) * (int)sizeof(float);  // ~66 KB
    cudaFuncSetAttribute(gemm_epi<128, 64, false>, cudaFuncAttributeMaxDynamicSharedMemorySize, smem1);
    cudaFuncSetAttribute(gemm_epi<128, 64, true>,  cudaFuncAttributeMaxDynamicSharedMemorySize, smem1);

    // g1 = dinv * (x @ W1i) -> bufA
    gemm_epi<128, 64, false><<<(N + 63) / 64, 256, smem1>>>(x, w1i, nullptr, pdinv, nullptr, pA, N);

    // S1 (bufB[0,64N)) = 0 ; scatter
    cudaMemsetAsync(pB, 0, (size_t)N * 64 * sizeof(float));
    {
        int total = E * 16;
        scatter_add<16><<<(total + 255) / 256, 256>>>(row, col, pA, pB, total);
    }
    // out1 = relu(dinv*S1 + x@W1r + b1) -> bufA (g1 dead)
    gemm_epi<128, 64, true><<<(N + 63) / 64, 256, smem1>>>(x, w1r, b1, pdinv, pB, pA, N);

    // ---- Layer 2 ----
    const int smem2 = (64 * 68 + 64 * 40) * (int)sizeof(float);    // ~27 KB
    float* pG2 = pB;                 // g2 in bufB[0,40N)
    float* pS2 = pB + (size_t)N * 40;  // S2 in bufB[40N,80N)

    // g2 = dinv * (out1 @ W2i)
    gemm_epi<64, 40, false><<<(N + 63) / 64, 160, smem2>>>(pA, w2i, nullptr, pdinv, nullptr, pG2, N);

    cudaMemsetAsync(pS2, 0, (size_t)N * 40 * sizeof(float));
    {
        int total = E * 10;
        scatter_add<10><<<(total + 255) / 256, 256>>>(row, col, pG2, pS2, total);
    }
    // out = relu(dinv*S2 + out1@W2r + b2) -> d_out
    gemm_epi<64, 40, true><<<(N + 63) / 64, 160, smem2>>>(pA, w2r, b2, pdinv, pS2, out, N);
}

// round 4
// speedup vs baseline: 1.1967x; 1.1967x over previous
#include <cuda_runtime.h>
#include <cuda_bf16.h>
#include <cstdint>

// ---------------------------------------------------------------------------
// BiARMA (2-layer ARMA GCN), N=100000, E=1e6, 128 -> 64 -> 40.
//
// dinv = rsqrt(deg(col)), 0 where deg==0
// g1   = dinv * (x @ W1i)            S1[c] += g1[r]  over edges
// out1 = relu(dinv*S1 + x @ W1r + b1)
// g2   = dinv * (out1 @ W2i)         S2[c] += g2[r]
// out  = relu(dinv*S2 + out1 @ W2r + b2)
//
// GEMMs on tensor cores: mma.sync.m16n8k16 bf16, 2-term split (hi+lo) for
// fp32-level accuracy:  acc += Ah*Bh + Ah*Bl + Al*Bh   (err ~1e-5 rel).
//
// Scratch (58 MB, tight VRAM headroom):
//   g_dinv [N]     deg then dinv (in place)
//   g_bufA [64N]   g1, later out1
//   g_bufB [80N]   S1 in [0,64N); then g2 in [0,40N) + S2 in [40N,80N)
// ---------------------------------------------------------------------------

static constexpr int MAXN = 100000;

__device__ float g_dinv[MAXN];
__device__ float g_bufA[MAXN * 64];
__device__ float g_bufB[MAXN * 80];

// ---------------------------------------------------------------------------
__global__ void deg_kernel(const int* __restrict__ col, float* __restrict__ deg, int E) {
    int i = blockIdx.x * blockDim.x + threadIdx.x;
    if (i < E) atomicAdd(&deg[col[i]], 1.0f);
}

__global__ void dinv_kernel(float* __restrict__ d, int N) {
    int i = blockIdx.x * blockDim.x + threadIdx.x;
    if (i < N) {
        float v = d[i];
        d[i] = (v > 0.0f) ? rsqrtf(v) : 0.0f;
    }
}

// ---------------------------------------------------------------------------
// Tensor-core GEMM with epilogue.
// X:[N,K] fp32 row-major, W:[K,NC] fp32 row-major.
// POST=false: O[n] = dinv[n] * (X@W)[n]
// POST=true : O[n] = relu(dinv[n]*S[n] + (X@W)[n] + b)
// Block: 128 nodes, 4 warps; warp covers 32 rows x NC cols.
// ---------------------------------------------------------------------------
#define MMA_BF16(c_, a_, b0_, b1_)                                          \
    asm volatile("mma.sync.aligned.m16n8k16.row.col.f32.bf16.bf16.f32 "     \
                 "{%0,%1,%2,%3}, {%4,%5,%6,%7}, {%8,%9}, {%0,%1,%2,%3};"    \
                 : "+f"((c_)[0]), "+f"((c_)[1]), "+f"((c_)[2]), "+f"((c_)[3]) \
                 : "r"((a_)[0]), "r"((a_)[1]), "r"((a_)[2]), "r"((a_)[3]),  \
                   "r"(b0_), "r"(b1_))

__device__ __forceinline__ void split_bf16(float v, __nv_bfloat16& h, __nv_bfloat16& l) {
    h = __float2bfloat16(v);
    l = __float2bfloat16(v - __bfloat162float(h));
}

template <int K, int NC, bool POST>
__global__ void __launch_bounds__(128)
gemm_mma(const float* __restrict__ X, const float* __restrict__ W,
         const float* __restrict__ Bias, const float* __restrict__ dinv,
         const float* __restrict__ S, float* __restrict__ O, int N)
{
    constexpr int SA = K + 8;          // padded k-stride (elements); conflict-free frags
    constexpr int NT = NC / 8;         // n-tiles per warp row

    extern __shared__ __nv_bfloat16 sm[];
    __nv_bfloat16* Ah = sm;                    // [128][SA]
    __nv_bfloat16* Al = Ah + 128 * SA;         // [128][SA]
    __nv_bfloat16* Bh = Al + 128 * SA;         // [NC][SA]  (W transposed: n-major)
    __nv_bfloat16* Bl = Bh + NC * SA;          // [NC][SA]

    const int tid  = threadIdx.x;
    const int base = blockIdx.x * 128;

    // ---- stage X tile (fp32 -> bf16 hi/lo) ----
    for (int idx = tid; idx < 128 * (K / 4); idx += 128) {
        int row = idx / (K / 4);
        int c4  = idx - row * (K / 4);
        int node = base + row;
        float4 v = (node < N) ? __ldg(reinterpret_cast<const float4*>(X + (size_t)node * K + c4 * 4))
                              : make_float4(0.f, 0.f, 0.f, 0.f);
        float vs[4] = {v.x, v.y, v.z, v.w};
        __nv_bfloat16 h[4], l[4];
#pragma unroll
        for (int j = 0; j < 4; j++) split_bf16(vs[j], h[j], l[j]);
        __nv_bfloat162* ph = reinterpret_cast<__nv_bfloat162*>(Ah + row * SA + c4 * 4);
        __nv_bfloat162* pl = reinterpret_cast<__nv_bfloat162*>(Al + row * SA + c4 * 4);
        ph[0] = __nv_bfloat162(h[0], h[1]); ph[1] = __nv_bfloat162(h[2], h[3]);
        pl[0] = __nv_bfloat162(l[0], l[1]); pl[1] = __nv_bfloat162(l[2], l[3]);
    }
    // ---- stage W transposed ----
    for (int i = tid; i < K * NC; i += 128) {
        int k = i / NC, n = i - k * NC;
        __nv_bfloat16 h, l;
        split_bf16(W[i], h, l);
        Bh[n * SA + k] = h;
        Bl[n * SA + k] = l;
    }
    __syncthreads();

    const int warp = tid >> 5, lane = tid & 31;
    const int g = lane >> 2, t = lane & 3;

    float acc[2][NT][4];
#pragma unroll
    for (int mt = 0; mt < 2; mt++)
#pragma unroll
        for (int nt = 0; nt < NT; nt++)
#pragma unroll
            for (int j = 0; j < 4; j++) acc[mt][nt][j] = 0.0f;

#pragma unroll 2
    for (int ks = 0; ks < K; ks += 16) {
        const int k0 = ks + t * 2;
        uint32_t a[2][2][4];   // [mtile][hi/lo][reg]
#pragma unroll
        for (int mt = 0; mt < 2; mt++) {
            int r0 = warp * 32 + mt * 16 + g;
            a[mt][0][0] = *reinterpret_cast<const uint32_t*>(Ah + r0 * SA + k0);
            a[mt][0][1] = *reinterpret_cast<const uint32_t*>(Ah + (r0 + 8) * SA + k0);
            a[mt][0][2] = *reinterpret_cast<const uint32_t*>(Ah + r0 * SA + k0 + 8);
            a[mt][0][3] = *reinterpret_cast<const uint32_t*>(Ah + (r0 + 8) * SA + k0 + 8);
            a[mt][1][0] = *reinterpret_cast<const uint32_t*>(Al + r0 * SA + k0);
            a[mt][1][1] = *reinterpret_cast<const uint32_t*>(Al + (r0 + 8) * SA + k0);
            a[mt][1][2] = *reinterpret_cast<const uint32_t*>(Al + r0 * SA + k0 + 8);
            a[mt][1][3] = *reinterpret_cast<const uint32_t*>(Al + (r0 + 8) * SA + k0 + 8);
        }
#pragma unroll
        for (int nt = 0; nt < NT; nt++) {
            int n0 = nt * 8 + g;
            uint32_t bh0 = *reinterpret_cast<const uint32_t*>(Bh + n0 * SA + k0);
            uint32_t bh1 = *reinterpret_cast<const uint32_t*>(Bh + n0 * SA + k0 + 8);
            uint32_t bl0 = *reinterpret_cast<const uint32_t*>(Bl + n0 * SA + k0);
            uint32_t bl1 = *reinterpret_cast<const uint32_t*>(Bl + n0 * SA + k0 + 8);
#pragma unroll
            for (int mt = 0; mt < 2; mt++) {
                MMA_BF16(acc[mt][nt], a[mt][0], bh0, bh1);   // Ah*Bh
                MMA_BF16(acc[mt][nt], a[mt][0], bl0, bl1);   // Ah*Bl
                MMA_BF16(acc[mt][nt], a[mt][1], bh0, bh1);   // Al*Bh
            }
        }
    }

    // ---- epilogue ----
#pragma unroll
    for (int mt = 0; mt < 2; mt++) {
        int r0 = base + warp * 32 + mt * 16 + g;   // rows r0 and r0+8
        int r1 = r0 + 8;
        float dv0 = (r0 < N) ? dinv[r0] : 0.0f;
        float dv1 = (r1 < N) ? dinv[r1] : 0.0f;
#pragma unroll
        for (int nt = 0; nt < NT; nt++) {
            int col = nt * 8 + t * 2;
            const float* a4 = acc[mt][nt];
            if (POST) {
                float2 bb = *reinterpret_cast<const float2*>(Bias + col);
                if (r0 < N) {
                    float2 s = *reinterpret_cast<const float2*>(S + (size_t)r0 * NC + col);
                    float2 o;
                    o.x = fmaxf(fmaf(dv0, s.x, a4[0] + bb.x), 0.0f);
                    o.y = fmaxf(fmaf(dv0, s.y, a4[1] + bb.y), 0.0f);
                    *reinterpret_cast<float2*>(O + (size_t)r0 * NC + col) = o;
                }
                if (r1 < N) {
                    float2 s = *reinterpret_cast<const float2*>(S + (size_t)r1 * NC + col);
                    float2 o;
                    o.x = fmaxf(fmaf(dv1, s.x, a4[2] + bb.x), 0.0f);
                    o.y = fmaxf(fmaf(dv1, s.y, a4[3] + bb.y), 0.0f);
                    *reinterpret_cast<float2*>(O + (size_t)r1 * NC + col) = o;
                }
            } else {
                if (r0 < N) {
                    float2 o = make_float2(a4[0] * dv0, a4[1] * dv0);
                    *reinterpret_cast<float2*>(O + (size_t)r0 * NC + col) = o;
                }
                if (r1 < N) {
                    float2 o = make_float2(a4[2] * dv1, a4[3] * dv1);
                    *reinterpret_cast<float2*>(O + (size_t)r1 * NC + col) = o;
                }
            }
        }
    }
}

// ---------------------------------------------------------------------------
// Edge scatter: S[col] += G[row]   (F = 4*FQ floats/node)
// One thread per (edge, float4 chunk); fire-and-forget vector reduction.
// ---------------------------------------------------------------------------
template <int FQ>
__global__ void scatter_add(const int* __restrict__ rowi, const int* __restrict__ coli,
                            const float* __restrict__ G, float* __restrict__ S, int total)
{
    int idx = blockIdx.x * blockDim.x + threadIdx.x;
    if (idx >= total) return;
    int e = idx / FQ;
    int c = idx - e * FQ;
    int r  = __ldg(rowi + e);
    int cl = __ldg(coli + e);
    float4 v = __ldg(reinterpret_cast<const float4*>(G + (r * FQ + c) * 4));
    float* p = S + (cl * FQ + c) * 4;
    asm volatile("red.global.add.v4.f32 [%0], {%1,%2,%3,%4};"
                 :: "l"(p), "f"(v.x), "f"(v.y), "f"(v.z), "f"(v.w) : "memory");
}

// ---------------------------------------------------------------------------
extern "C" void kernel_launch(void* const* d_in, const int* in_sizes, int n_in,
                              void* d_out, int out_size)
{
    const float* x   = (const float*)d_in[0];
    const int*   ei  = (const int*)  d_in[1];
    const float* w1i = (const float*)d_in[2];
    const float* w1r = (const float*)d_in[3];
    const float* b1  = (const float*)d_in[4];
    const float* w2i = (const float*)d_in[5];
    const float* w2r = (const float*)d_in[6];
    const float* b2  = (const float*)d_in[7];
    float* out = (float*)d_out;

    const int E = in_sizes[1] / 2;
    const int N = out_size / 40;
    const int* row = ei;
    const int* col = ei + E;

    float *pdinv, *pA, *pB;
    cudaGetSymbolAddress((void**)&pdinv, g_dinv);
    cudaGetSymbolAddress((void**)&pA,    g_bufA);
    cudaGetSymbolAddress((void**)&pB,    g_bufB);

    // deg -> dinv (in place)
    cudaMemsetAsync(pdinv, 0, (size_t)N * sizeof(float));
    deg_kernel <<<(E + 255) / 256, 256>>>(col, pdinv, E);
    dinv_kernel<<<(N + 255) / 256, 256>>>(pdinv, N);

    const int grid = (N + 127) / 128;

    // ---- Layer 1 (K=128, NC=64): smem = (2*128 + 2*64) * 136 * 2B = 104448 B
    const int smem1 = (2 * 128 + 2 * 64) * (128 + 8) * (int)sizeof(__nv_bfloat16);
    cudaFuncSetAttribute(gemm_mma<128, 64, false>, cudaFuncAttributeMaxDynamicSharedMemorySize, smem1);
    cudaFuncSetAttribute(gemm_mma<128, 64, true>,  cudaFuncAttributeMaxDynamicSharedMemorySize, smem1);

    // g1 = dinv * (x @ W1i) -> bufA
    gemm_mma<128, 64, false><<<grid, 128, smem1>>>(x, w1i, nullptr, pdinv, nullptr, pA, N);

    // S1 (bufB[0,64N)) = 0 ; scatter
    cudaMemsetAsync(pB, 0, (size_t)N * 64 * sizeof(float));
    {
        int total = E * 16;
        scatter_add<16><<<(total + 255) / 256, 256>>>(row, col, pA, pB, total);
    }
    // out1 = relu(dinv*S1 + x@W1r + b1) -> bufA (g1 dead)
    gemm_mma<128, 64, true><<<grid, 128, smem1>>>(x, w1r, b1, pdinv, pB, pA, N);

    // ---- Layer 2 (K=64, NC=40): smem = (2*128 + 2*40) * 72 * 2B = 48384 B
    const int smem2 = (2 * 128 + 2 * 40) * (64 + 8) * (int)sizeof(__nv_bfloat16);
    float* pG2 = pB;                     // g2 in bufB[0,40N)
    float* pS2 = pB + (size_t)N * 40;    // S2 in bufB[40N,80N)

    // g2 = dinv * (out1 @ W2i)
    gemm_mma<64, 40, false><<<grid, 128, smem2>>>(pA, w2i, nullptr, pdinv, nullptr, pG2, N);

    cudaMemsetAsync(pS2, 0, (size_t)N * 40 * sizeof(float));
    {
        int total = E * 10;
        scatter_add<10><<<(total + 255) / 256, 256>>>(row, col, pG2, pS2, total);
    }
    // out = relu(dinv*S2 + out1@W2r + b2) -> d_out
    gemm_mma<64, 40, true><<<grid, 128, smem2>>>(pA, w2r, b2, pdinv, pS2, out, N);
}